// round 9
// baseline (speedup 1.0000x reference)
#include <cuda_runtime.h>
#include <cstdint>

#define NUM_ITEMS 6714
#define BATCH_MAX 8192
#define RANK 100
#define NTHREADS 256
#define NWARPS 8
#define THRESH_F 2.0f      // count(>=2.0) ~ 153 +/- 12 per row for N(0,1) rows
#define SLOTS 256
#define MAXWRED 40

__device__ int g_cnt[BATCH_MAX];                          // zero-initialized at load
__device__ unsigned long long g_cand[BATCH_MAX * SLOTS];  // scratch candidates

__device__ __forceinline__ uint32_t flip_f32(uint32_t s) {
    return s ^ ((s & 0x80000000u) ? 0xFFFFFFFFu : 0x80000000u);
}
__device__ __forceinline__ float unflip_f32(uint32_t k) {
    uint32_t s = (k & 0x80000000u) ? (k ^ 0x80000000u) : ~k;
    return __uint_as_float(s);
}

__device__ __forceinline__ void emit_hit(float f, uint32_t e) {
    uint32_t row = e / NUM_ITEMS;                 // constant division -> mulhi
    uint32_t col = e - row * NUM_ITEMS;
    uint32_t key = flip_f32(__float_as_uint(f));
    uint32_t pos = (uint32_t)atomicAdd(&g_cnt[row], 1);
    if (pos < SLOTS)
        g_cand[row * SLOTS + pos] = ((unsigned long long)(~key) << 32) | col;
}

// ---- Kernel A: streaming filter over the whole matrix ----
__global__ __launch_bounds__(NTHREADS) void filter_kernel(
    const float* __restrict__ in, uint32_t n4, uint32_t total)
{
    const float4* in4 = reinterpret_cast<const float4*>(in);
    const uint32_t stride = gridDim.x * blockDim.x;
    for (uint32_t i = blockIdx.x * blockDim.x + threadIdx.x; i < n4; i += stride) {
        float4 v = in4[i];
        if (v.x >= THRESH_F || v.y >= THRESH_F || v.z >= THRESH_F || v.w >= THRESH_F) {
            if (v.x >= THRESH_F) emit_hit(v.x, 4u * i + 0u);
            if (v.y >= THRESH_F) emit_hit(v.y, 4u * i + 1u);
            if (v.z >= THRESH_F) emit_hit(v.z, 4u * i + 2u);
            if (v.w >= THRESH_F) emit_hit(v.w, 4u * i + 3u);
        }
    }
    // scalar tail (total % 4 elements), single thread
    if (blockIdx.x == 0 && threadIdx.x == 0) {
        for (uint32_t e = 4u * n4; e < total; ++e) {
            float f = in[e];
            if (f >= THRESH_F) emit_hit(f, e);
        }
    }
}

// ---- Kernel B: per-row exact top-100 from candidate set ----
struct SharedB {
    alignas(16) unsigned long long fin[SLOTS];
    uint32_t wred[MAXWRED][NWARPS];
    uint32_t cntF;
    int found;
    float labelval;
};

__global__ __launch_bounds__(NTHREADS) void select_kernel(
    const float* __restrict__ output,
    const int* __restrict__ labels,
    float* __restrict__ out_vals,
    float* __restrict__ out_labels)
{
    __shared__ SharedB s;

    const int row  = blockIdx.x;
    const int tid  = threadIdx.x;
    const int lane = tid & 31;
    const int wid  = tid >> 5;
    const float* row_ptr = output + (size_t)row * NUM_ITEMS;
    const int label = labels[row];
    const int cnt = g_cnt[row];

    if (tid == 0) {
        s.found = -1;
        s.cntF = 0u;
        s.labelval = row_ptr[label];
    }
    __syncthreads();

    uint32_t cntN;
    if (cnt >= RANK && cnt <= SLOTS) {
        // ---- common path: one candidate per thread from scratch ----
        cntN = (uint32_t)cnt;
        if (tid < cnt) s.fin[tid] = g_cand[(size_t)row * SLOTS + tid];
        else           s.fin[tid] = ~0ull;          // sentinel pad up to 256
    } else {
        // ---- fallback: exact bit-narrowing over the full row (rare/never) ----
        uint32_t pfx = 0u, k = RANK, cand = NUM_ITEMS;
        int sh = 31, iter = 0;
        while (cand > (SLOTS - RANK) && sh >= 0 && iter < MAXWRED) {
            const uint32_t t = (pfx << 1) | 1u;
            int c = 0;
            for (int i = tid; i < NUM_ITEMS; i += NTHREADS)
                c += ((flip_f32(__float_as_uint(row_ptr[i])) >> sh) == t);
            c = __reduce_add_sync(0xFFFFFFFFu, c);
            if (lane == 0) s.wred[iter][wid] = (uint32_t)c;
            __syncthreads();
            uint32_t cnt1 = 0;
            #pragma unroll
            for (int w = 0; w < NWARPS; ++w) cnt1 += s.wred[iter][w];
            if (cnt1 >= k) { pfx = t; cand = cnt1; }
            else           { k -= cnt1; pfx <<= 1; cand -= cnt1; }
            --sh; ++iter;
        }
        const uint32_t tf = (sh >= 31) ? 0u : (pfx << (sh + 1));
        s.fin[tid] = ~0ull;
        __syncthreads();
        for (int i = tid; i < NUM_ITEMS; i += NTHREADS) {
            uint32_t key = flip_f32(__float_as_uint(row_ptr[i]));
            if (key >= tf) {
                uint32_t pos = atomicAdd(&s.cntF, 1u);   // plain atomics only
                if (pos < SLOTS)
                    s.fin[pos] = ((unsigned long long)(~key) << 32) | (uint32_t)i;
            }
        }
        __syncthreads();
        cntN = min(s.cntF, (uint32_t)SLOTS);
    }
    __syncthreads();

    const uint32_t cntP = (cntN + 3u) & ~3u;        // <= 256; pad region is sentinel

    // ---- exact rank: vec4 O(n^2), one candidate per thread ----
    unsigned long long p64 = s.fin[tid];
    const uint4* f4 = reinterpret_cast<const uint4*>(s.fin);
    int r = 0;
    const uint32_t n4 = cntP >> 2;
    for (uint32_t i = 0; i < n4; ++i) {
        uint4 a = f4[2 * i];
        uint4 b = f4[2 * i + 1];
        unsigned long long c0 = ((unsigned long long)a.y << 32) | a.x;
        unsigned long long c1 = ((unsigned long long)a.w << 32) | a.z;
        unsigned long long c2 = ((unsigned long long)b.y << 32) | b.x;
        unsigned long long c3 = ((unsigned long long)b.w << 32) | b.z;
        r += (int)(c0 < p64) + (int)(c1 < p64) + (int)(c2 < p64) + (int)(c3 < p64);
    }

    float* out_row = out_vals + (size_t)row * RANK;
    if (tid < (int)cntN && r < RANK) {
        int j = (RANK - 1) - r;
        out_row[j] = unflip_f32(~(uint32_t)(p64 >> 32));
        if ((uint32_t)(p64 & 0xFFFFFFFFu) == (uint32_t)label)
            s.found = j;                             // unique writer
    }
    __syncthreads();

    if (tid == 0) {
        int found = s.found;
        if (found < 0) out_row[0] = s.labelval;      // substitute missing label
        out_labels[row] = (float)(found < 0 ? 0 : found);
        g_cnt[row] = 0;                              // reset for next graph replay
    }
}

extern "C" void kernel_launch(void* const* d_in, const int* in_sizes, int n_in,
                              void* d_out, int out_size) {
    const float* output = (const float*)d_in[0];
    const int*   labels = (const int*)d_in[1];
    const int batch = in_sizes[1];

    float* out_vals   = (float*)d_out;
    float* out_labels = out_vals + (size_t)batch * RANK;

    const uint32_t total = (uint32_t)batch * NUM_ITEMS;
    const uint32_t n4 = total / 4u;

    filter_kernel<<<2048, NTHREADS>>>(output, n4, total);
    select_kernel<<<batch, NTHREADS>>>(output, labels, out_vals, out_labels);
}

// round 10
// speedup vs baseline: 2.3018x; 2.3018x over previous
#include <cuda_runtime.h>
#include <cstdint>
#include <math.h>

#define NUM_ITEMS 6714
#define N2 3357            // float2 per row
#define TAIL2 29           // N2 - 13*256
#define RANK 100
#define NTHREADS 256
#define NWARPS 8
#define KPT 14
#define THRESH_F 2.0f      // count(>=2.0) ~ 153 +/- 12 per row for this data
#define CAND_CAP 1024
#define STOPF 156          // fallback narrow target: total <= 100+156 = 256
#define MAXITER 40

__device__ __forceinline__ uint32_t flip_f32(uint32_t s) {
    return s ^ ((s & 0x80000000u) ? 0xFFFFFFFFu : 0x80000000u);
}
__device__ __forceinline__ float unflip_f32(uint32_t k) {
    uint32_t s = (k & 0x80000000u) ? (k ^ 0x80000000u) : ~k;
    return __uint_as_float(s);
}

struct Shared {
    alignas(16) unsigned long long cand[CAND_CAP]; // ((u64)(~key)<<32)|idx ; reused as bin-sorted
    uint32_t hist[256];
    uint32_t pfx[256];
    uint32_t binpos[256];
    uint32_t wmin[NWARPS], wmax[NWARPS];
    uint32_t wred[2][NWARPS];
    uint32_t cnt0;
    uint32_t hmin, hmax;
    int found;
    float labelval;
};

__global__ __launch_bounds__(NTHREADS) void logit_selector_kernel(
    const float* __restrict__ output,
    const int* __restrict__ labels,
    float* __restrict__ out_vals,
    float* __restrict__ out_labels)
{
    __shared__ Shared s;

    const int row  = blockIdx.x;
    const int tid  = threadIdx.x;
    const int lane = tid & 31;
    const int wid  = tid >> 5;
    const float* row_ptr = output + (size_t)row * NUM_ITEMS;
    const float2* row2 = reinterpret_cast<const float2*>(row_ptr);
    const int label = labels[row];

    // ---- front-batched load: 13 unchecked + 1 checked float2 (MLP ~14) ----
    float2 v[KPT];
    #pragma unroll
    for (int j = 0; j < KPT - 1; ++j)
        v[j] = row2[tid + j * NTHREADS];
    if (tid < TAIL2) v[KPT - 1] = row2[tid + (KPT - 1) * NTHREADS];
    else { v[KPT - 1].x = -INFINITY; v[KPT - 1].y = -INFINITY; }

    if (tid == 0) { s.cnt0 = 0u; s.found = -1; s.labelval = row_ptr[label]; }
    __syncthreads();

    // ---- order-free compact: per-thread hit count -> warp scan -> 1 atomic/warp ----
    uint32_t nh = 0;
    #pragma unroll
    for (int j = 0; j < KPT; ++j)
        nh += (uint32_t)(v[j].x >= THRESH_F) + (uint32_t)(v[j].y >= THRESH_F);

    uint32_t inc = nh;
    #pragma unroll
    for (int o = 1; o < 32; o <<= 1) {
        uint32_t u = __shfl_up_sync(0xFFFFFFFFu, inc, o);
        if (lane >= o) inc += u;
    }
    uint32_t wbase = 0;
    if (lane == 31) wbase = atomicAdd(&s.cnt0, inc);   // inc@lane31 == warp total
    wbase = __shfl_sync(0xFFFFFFFFu, wbase, 31);
    uint32_t mypos = wbase + (inc - nh);               // exclusive offset

    #pragma unroll
    for (int j = 0; j < KPT; ++j) {
        int i2 = tid + j * NTHREADS;
        if (v[j].x >= THRESH_F) {
            uint32_t key = flip_f32(__float_as_uint(v[j].x));
            if (mypos < CAND_CAP)
                s.cand[mypos] = ((unsigned long long)(~key) << 32) | (uint32_t)(2 * i2);
            ++mypos;
        }
        if (v[j].y >= THRESH_F) {
            uint32_t key = flip_f32(__float_as_uint(v[j].y));
            if (mypos < CAND_CAP)
                s.cand[mypos] = ((unsigned long long)(~key) << 32) | (uint32_t)(2 * i2 + 1);
            ++mypos;
        }
    }
    __syncthreads();
    uint32_t cnt0 = s.cnt0;

    // ---- fallback: exact bit-narrowing reading global (never on this data) ----
    if (cnt0 < RANK || cnt0 > CAND_CAP) {
        __syncthreads();
        if (tid == 0) s.cnt0 = 0u;
        __syncthreads();
        uint32_t pfx32 = 0u, k = RANK, cand = NUM_ITEMS;
        int sh = 31, iter = 0;
        while (cand > STOPF && sh >= 0 && iter < MAXITER) {
            const uint32_t t = (pfx32 << 1) | 1u;
            int c = 0;
            for (int i = tid; i < NUM_ITEMS; i += NTHREADS)
                c += ((flip_f32(__float_as_uint(row_ptr[i])) >> sh) == t);
            c = __reduce_add_sync(0xFFFFFFFFu, c);     // reconverged after loop
            if (lane == 0) s.wred[iter & 1][wid] = (uint32_t)c;
            __syncthreads();
            uint32_t cnt1 = 0;
            #pragma unroll
            for (int w = 0; w < NWARPS; ++w) cnt1 += s.wred[iter & 1][w];
            if (cnt1 >= k) { pfx32 = t; cand = cnt1; }
            else           { k -= cnt1; pfx32 <<= 1; cand -= cnt1; }
            --sh; ++iter;
        }
        const uint32_t tf = (sh >= 31) ? 0u : (pfx32 << (sh + 1));
        for (int i = tid; i < NUM_ITEMS; i += NTHREADS) {
            uint32_t key = flip_f32(__float_as_uint(row_ptr[i]));
            if (key >= tf) {
                uint32_t pos = atomicAdd(&s.cnt0, 1u);
                if (pos < CAND_CAP)
                    s.cand[pos] = ((unsigned long long)(~key) << 32) | (uint32_t)i;
            }
        }
        __syncthreads();
        cnt0 = min(s.cnt0, (uint32_t)CAND_CAP);
    }
    const uint32_t cntN = cnt0;

    // ---- bucket rank: gather my candidates into registers ----
    unsigned long long p[4];
    uint32_t bin[4];
    int nb = 0;
    #pragma unroll
    for (int i = 0; i < 4; ++i) {
        uint32_t c = (uint32_t)tid + (uint32_t)i * NTHREADS;
        if (c < cntN) { p[i] = s.cand[c]; ++nb; }
    }

    // min/max of candidate high words
    uint32_t lo_ = 0xFFFFFFFFu, hi_ = 0u;
    #pragma unroll
    for (int i = 0; i < 4; ++i)
        if (i < nb) {
            uint32_t h = (uint32_t)(p[i] >> 32);
            lo_ = min(lo_, h); hi_ = max(hi_, h);
        }
    #pragma unroll
    for (int o = 16; o > 0; o >>= 1) {
        lo_ = min(lo_, __shfl_xor_sync(0xFFFFFFFFu, lo_, o));
        hi_ = max(hi_, __shfl_xor_sync(0xFFFFFFFFu, hi_, o));
    }
    if (lane == 0) { s.wmin[wid] = lo_; s.wmax[wid] = hi_; }
    s.hist[tid] = 0u;
    __syncthreads();
    if (tid == 0) {
        uint32_t mn = 0xFFFFFFFFu, mx = 0u;
        #pragma unroll
        for (int w = 0; w < NWARPS; ++w) { mn = min(mn, s.wmin[w]); mx = max(mx, s.wmax[w]); }
        s.hmin = mn; s.hmax = mx;
    }
    __syncthreads();
    const uint32_t hmin = s.hmin;
    const float recip = 255.0f / fmaxf(1.0f, (float)(s.hmax - hmin));

    // histogram (monotone binning: bin nondecreasing in high word)
    #pragma unroll
    for (int i = 0; i < 4; ++i)
        if (i < nb) {
            uint32_t h = (uint32_t)(p[i] >> 32);
            bin[i] = min(255u, (uint32_t)((float)(h - hmin) * recip));
            atomicAdd(&s.hist[bin[i]], 1u);
        }
    __syncthreads();

    // exclusive prefix sum over 256 bins
    {
        uint32_t hv = s.hist[tid];
        uint32_t ic = hv;
        #pragma unroll
        for (int o = 1; o < 32; o <<= 1) {
            uint32_t u = __shfl_up_sync(0xFFFFFFFFu, ic, o);
            if (lane >= o) ic += u;
        }
        if (lane == 31) s.wred[0][wid] = ic;
        __syncthreads();
        uint32_t wadd = 0;
        #pragma unroll
        for (int w = 0; w < NWARPS; ++w)
            if (w < wid) wadd += s.wred[0][w];
        uint32_t excl = wadd + ic - hv;
        s.pfx[tid] = excl;
        s.binpos[tid] = excl;
    }
    __syncthreads();

    // scatter into bin-sorted order (cand reused; all reads completed above)
    #pragma unroll
    for (int i = 0; i < 4; ++i)
        if (i < nb) {
            uint32_t pos = atomicAdd(&s.binpos[bin[i]], 1u);
            s.cand[pos] = p[i];
        }
    __syncthreads();

    // refine within bin + write outputs
    float* out_row = out_vals + (size_t)row * RANK;
    #pragma unroll
    for (int i = 0; i < 4; ++i)
        if (i < nb) {
            uint32_t b = bin[i];
            uint32_t base = s.pfx[b];
            uint32_t m = s.hist[b];
            uint32_t r = base;
            for (uint32_t t2 = 0; t2 < m; ++t2)
                r += (s.cand[base + t2] < p[i]);
            if (r < RANK) {
                int j = (RANK - 1) - (int)r;
                out_row[j] = unflip_f32(~(uint32_t)(p[i] >> 32));
                if ((uint32_t)(p[i] & 0xFFFFFFFFu) == (uint32_t)label)
                    s.found = j;                       // unique writer
            }
        }
    __syncthreads();

    if (tid == 0) {
        int found = s.found;
        if (found < 0) out_row[0] = s.labelval;        // substitute missing label at col 0
        out_labels[row] = (float)(found < 0 ? 0 : found);
    }
}

extern "C" void kernel_launch(void* const* d_in, const int* in_sizes, int n_in,
                              void* d_out, int out_size) {
    const float* output = (const float*)d_in[0];
    const int*   labels = (const int*)d_in[1];
    const int batch = in_sizes[1];

    float* out_vals   = (float*)d_out;
    float* out_labels = out_vals + (size_t)batch * RANK;

    logit_selector_kernel<<<batch, NTHREADS>>>(output, labels, out_vals, out_labels);
}